// round 7
// baseline (speedup 1.0000x reference)
#include <cuda_runtime.h>
#include <cstdint>

#define HD 128
#define NMAX 100000
#define EMAX 800000
#define SCAN_CHUNK 1024
#define NBLK ((NMAX + SCAN_CHUNK - 1) / SCAN_CHUNK)

// ---------------- scratch ----------------
__device__ __align__(256) float g_L[(size_t)NMAX * HD];
__device__ __align__(256) float g_G[(size_t)NMAX * HD];
__device__ __align__(256) float g_dinv[NMAX];
__device__ __align__(256) float g_selfw[NMAX];
__device__ __align__(256) int   g_cnt[NMAX];
__device__ __align__(256) int   g_rowptr[NMAX + 1];
__device__ __align__(256) int   g_cursor[NMAX];
__device__ __align__(256) int   g_csrc[EMAX];
__device__ __align__(256) float g_cw[EMAX];
__device__ __align__(256) int   g_bsum[NBLK];
__device__ __align__(256) int   g_boff[NBLK];
__device__ __align__(256) float g_sum[HD];
__device__ __align__(256) float g_sq[HD];
__device__ __align__(256) float g_scale[HD];
__device__ __align__(256) float g_shift[HD];

// ---------------- CSR build ----------------
__global__ void k_zero_cnt(int N) {
    int i = blockIdx.x * blockDim.x + threadIdx.x;
    if (i < N) g_cnt[i] = 0;
}
__global__ void k_hist(const int* __restrict__ ei, int E) {
    int e = blockIdx.x * blockDim.x + threadIdx.x;
    if (e < E) atomicAdd(&g_cnt[ei[E + e]], 1);
}
__global__ void k_dinv(int N) {
    int i = blockIdx.x * blockDim.x + threadIdx.x;
    if (i < N) {
        float dv = rsqrtf((float)g_cnt[i] + 1.0f);
        g_dinv[i]  = dv;
        g_selfw[i] = dv * dv;
    }
}
__global__ void __launch_bounds__(256) k_blocksum(int N) {
    __shared__ int wsum[8];
    int tid  = threadIdx.x;
    int base = blockIdx.x * SCAN_CHUNK + tid * 4;
    int s = 0;
#pragma unroll
    for (int j = 0; j < 4; j++) {
        int i = base + j;
        if (i < N) s += g_cnt[i];
    }
#pragma unroll
    for (int off = 16; off > 0; off >>= 1)
        s += __shfl_down_sync(0xFFFFFFFF, s, off);
    if ((tid & 31) == 0) wsum[tid >> 5] = s;
    __syncthreads();
    if (tid == 0) {
        int t = 0;
#pragma unroll
        for (int w = 0; w < 8; w++) t += wsum[w];
        g_bsum[blockIdx.x] = t;
    }
}
__global__ void __launch_bounds__(128) k_scan_bsum(int E, int N) {
    __shared__ int sv[NBLK];
    int tid = threadIdx.x;
    if (tid < NBLK) sv[tid] = g_bsum[tid];
    __syncthreads();
    if (tid == 0) {
        int run = 0;
        for (int i = 0; i < NBLK; i++) {
            g_boff[i] = run;
            run += sv[i];
        }
        g_rowptr[N] = E;
    }
}
__global__ void __launch_bounds__(256) k_emit(int N) {
    __shared__ int wexc[8];
    int tid  = threadIdx.x;
    int lane = tid & 31;
    int wid  = tid >> 5;
    int base = blockIdx.x * SCAN_CHUNK + tid * 4;
    int c[4];
#pragma unroll
    for (int j = 0; j < 4; j++) {
        int i = base + j;
        c[j] = (i < N) ? g_cnt[i] : 0;
    }
    int tsum = c[0] + c[1] + c[2] + c[3];
    int inc = tsum;
#pragma unroll
    for (int off = 1; off < 32; off <<= 1) {
        int v = __shfl_up_sync(0xFFFFFFFF, inc, off);
        if (lane >= off) inc += v;
    }
    if (lane == 31) wexc[wid] = inc;
    __syncthreads();
    if (tid == 0) {
        int run = 0;
#pragma unroll
        for (int w = 0; w < 8; w++) {
            int t = wexc[w];
            wexc[w] = run;
            run += t;
        }
    }
    __syncthreads();
    int run = g_boff[blockIdx.x] + wexc[wid] + (inc - tsum);
#pragma unroll
    for (int j = 0; j < 4; j++) {
        int i = base + j;
        if (i < N) {
            g_rowptr[i] = run;
            g_cursor[i] = run;
            run += c[j];
        }
    }
}
__global__ void k_fill(const int* __restrict__ ei, int E) {
    int e = blockIdx.x * blockDim.x + threadIdx.x;
    if (e < E) {
        int s = ei[e], d = ei[E + e];
        int pos = atomicAdd(&g_cursor[d], 1);
        g_csrc[pos] = s;
        g_cw[pos]   = g_dinv[s] * g_dinv[d];
    }
}

// ---------------- tf32 helpers ----------------
__device__ __forceinline__ void split_tf32(float f, uint32_t& hi, uint32_t& lo) {
    asm("cvt.rna.tf32.f32 %0, %1;" : "=r"(hi) : "f"(f));
    float r = f - __uint_as_float(hi);
    asm("cvt.rna.tf32.f32 %0, %1;" : "=r"(lo) : "f"(r));
}
__device__ __forceinline__ void mma_tf32(float* c, const uint32_t* a, const uint32_t* b) {
    asm volatile(
        "mma.sync.aligned.m16n8k8.row.col.f32.tf32.tf32.f32 "
        "{%0,%1,%2,%3}, {%4,%5,%6,%7}, {%8,%9}, {%0,%1,%2,%3};"
        : "+f"(c[0]), "+f"(c[1]), "+f"(c[2]), "+f"(c[3])
        : "r"(a[0]), "r"(a[1]), "r"(a[2]), "r"(a[3]), "r"(b[0]), "r"(b[1]));
}

// ---------------- GEMM: L = act(A) @ W (tensor core, 3xTF32) ----------------
// bn=0: act = identity; bn=1: act = relu(scale*A + shift)
#define AS_STRIDE 132
#define BS_STRIDE 136
#define GEMM_SMEM ((128 * AS_STRIDE + 128 * BS_STRIDE) * 4)

__global__ void __launch_bounds__(256) k_gemm(const float* __restrict__ A,
                                              const float* __restrict__ W,
                                              float* __restrict__ L, int N, int bn) {
    extern __shared__ float sm[];
    float* As = sm;                    // [row][k]  stride 132
    float* Bs = sm + 128 * AS_STRIDE;  // [k][col]  stride 136

    int tid   = threadIdx.x;
    int lane  = tid & 31;
    int wid   = tid >> 5;
    int rbase = blockIdx.x * 128;

    // stage A (with optional BN+ReLU on features) and W
    for (int i = tid; i < 4096; i += 256) {
        int row = i >> 5, q = i & 31;
        int gr = rbase + row;
        float4 v = make_float4(0.f, 0.f, 0.f, 0.f);
        if (gr < N) v = ((const float4*)(A + (size_t)gr * HD))[q];
        if (bn) {
            float4 sc = ((const float4*)g_scale)[q];
            float4 sh = ((const float4*)g_shift)[q];
            v.x = fmaxf(v.x * sc.x + sh.x, 0.f);
            v.y = fmaxf(v.y * sc.y + sh.y, 0.f);
            v.z = fmaxf(v.z * sc.z + sh.z, 0.f);
            v.w = fmaxf(v.w * sc.w + sh.w, 0.f);
        }
        *(float4*)&As[row * AS_STRIDE + q * 4] = v;
    }
    for (int i = tid; i < 4096; i += 256) {
        int k = i >> 5, q = i & 31;
        float4 v = ((const float4*)W)[i];
        *(float4*)&Bs[k * BS_STRIDE + q * 4] = v;
    }
    __syncthreads();

    // warp tiling: 8 warps = 4 (row) x 2 (col); warp tile 32 rows x 64 cols
    int wrow = wid >> 1, wcol = wid & 1;
    int R = wrow * 32, C = wcol * 64;
    int grp = lane >> 2, kq = lane & 3;

    float acc[2][8][4];
#pragma unroll
    for (int m = 0; m < 2; m++)
#pragma unroll
        for (int j = 0; j < 8; j++)
#pragma unroll
            for (int t = 0; t < 4; t++) acc[m][j][t] = 0.f;

#pragma unroll 1
    for (int step = 0; step < 16; step++) {
        int k0 = step * 8;
        uint32_t Ahi[2][4], Alo[2][4], Bhi[8][2], Blo[8][2];
#pragma unroll
        for (int m = 0; m < 2; m++) {
            int r = R + m * 16 + grp;
            split_tf32(As[(r)     * AS_STRIDE + k0 + kq],     Ahi[m][0], Alo[m][0]);
            split_tf32(As[(r + 8) * AS_STRIDE + k0 + kq],     Ahi[m][1], Alo[m][1]);
            split_tf32(As[(r)     * AS_STRIDE + k0 + kq + 4], Ahi[m][2], Alo[m][2]);
            split_tf32(As[(r + 8) * AS_STRIDE + k0 + kq + 4], Ahi[m][3], Alo[m][3]);
        }
#pragma unroll
        for (int j = 0; j < 8; j++) {
            int cn = C + j * 8 + grp;
            split_tf32(Bs[(k0 + kq)     * BS_STRIDE + cn], Bhi[j][0], Blo[j][0]);
            split_tf32(Bs[(k0 + kq + 4) * BS_STRIDE + cn], Bhi[j][1], Blo[j][1]);
        }
#pragma unroll
        for (int m = 0; m < 2; m++)
#pragma unroll
            for (int j = 0; j < 8; j++) {
                mma_tf32(acc[m][j], Ahi[m], Bhi[j]);
                mma_tf32(acc[m][j], Alo[m], Bhi[j]);
                mma_tf32(acc[m][j], Ahi[m], Blo[j]);
            }
    }

    // writeback: thread owns (row=grp, col=2kq),(+1) and (row+8, ...)
#pragma unroll
    for (int m = 0; m < 2; m++) {
        int r0 = rbase + R + m * 16 + grp;
#pragma unroll
        for (int j = 0; j < 8; j++) {
            int col = C + j * 8 + 2 * kq;
            if (r0 < N)
                *(float2*)&L[(size_t)r0 * HD + col] = make_float2(acc[m][j][0], acc[m][j][1]);
            if (r0 + 8 < N)
                *(float2*)&L[(size_t)(r0 + 8) * HD + col] = make_float2(acc[m][j][2], acc[m][j][3]);
        }
    }
}

// ---------------- aggregate + fused BN stats ----------------
// G[row] = selfw*L[row] + bias + sum_e w*L[src]; block accumulates sum/sumsq
__global__ void __launch_bounds__(256) k_aggregate(const float* __restrict__ L,
                                                   const float* __restrict__ bias,
                                                   float* __restrict__ G, int N) {
    __shared__ float ssum[HD];
    __shared__ float ssq[HD];
    int tid  = threadIdx.x;
    int wid  = tid >> 5;
    int lane = tid & 31;
    int row  = blockIdx.x * 8 + wid;

    if (tid < HD) ssum[tid] = 0.f;
    else          ssq[tid - HD] = 0.f;
    __syncthreads();

    if (row < N) {
        float4 b  = ((const float4*)bias)[lane];
        float  sw = g_selfw[row];
        float4 sv = ((const float4*)(L + (size_t)row * HD))[lane];
        float4 acc;
        acc.x = sv.x * sw + b.x;
        acc.y = sv.y * sw + b.y;
        acc.z = sv.z * sw + b.z;
        acc.w = sv.w * sw + b.w;

        int p0 = g_rowptr[row], p1 = g_rowptr[row + 1];
        for (int p = p0; p < p1; p++) {
            int   s = g_csrc[p];
            float w = g_cw[p];
            float4 v = ((const float4*)(L + (size_t)s * HD))[lane];
            acc.x += v.x * w;
            acc.y += v.y * w;
            acc.z += v.z * w;
            acc.w += v.w * w;
        }
        ((float4*)(G + (size_t)row * HD))[lane] = acc;

        int c = lane * 4;
        atomicAdd(&ssum[c + 0], acc.x);
        atomicAdd(&ssum[c + 1], acc.y);
        atomicAdd(&ssum[c + 2], acc.z);
        atomicAdd(&ssum[c + 3], acc.w);
        atomicAdd(&ssq[c + 0], acc.x * acc.x);
        atomicAdd(&ssq[c + 1], acc.y * acc.y);
        atomicAdd(&ssq[c + 2], acc.z * acc.z);
        atomicAdd(&ssq[c + 3], acc.w * acc.w);
    }
    __syncthreads();
    if (tid < HD) atomicAdd(&g_sum[tid], ssum[tid]);
    else          atomicAdd(&g_sq[tid - HD], ssq[tid - HD]);
}

// ---------------- BN ----------------
__global__ void k_zero_stats() {
    int c = threadIdx.x;
    g_sum[c] = 0.f;
    g_sq[c]  = 0.f;
}
__global__ void k_bn_final(const float* __restrict__ gamma, const float* __restrict__ beta, int N) {
    int c = threadIdx.x;
    float invn = 1.0f / (float)N;
    float mu   = g_sum[c] * invn;
    float var  = g_sq[c] * invn - mu * mu;
    float sc   = gamma[c] * rsqrtf(var + 1e-5f);
    g_scale[c] = sc;
    g_shift[c] = beta[c] - mu * sc;
}

// ---------------- query ----------------
__global__ void k_query(const float* __restrict__ G, const int* __restrict__ eli,
                        float* __restrict__ out, int Q) {
    int gtid = blockIdx.x * blockDim.x + threadIdx.x;
    int q    = gtid >> 5;
    int lane = gtid & 31;
    if (q >= Q) return;
    int u = eli[q];
    int v = eli[Q + q];
    float4 sc = ((const float4*)g_scale)[lane];
    float4 sh = ((const float4*)g_shift)[lane];
    float4 a = ((const float4*)(G + (size_t)u * HD))[lane];
    float4 b = ((const float4*)(G + (size_t)v * HD))[lane];
    a.x = a.x * sc.x + sh.x; a.y = a.y * sc.y + sh.y;
    a.z = a.z * sc.z + sh.z; a.w = a.w * sc.w + sh.w;
    b.x = b.x * sc.x + sh.x; b.y = b.y * sc.y + sh.y;
    b.z = b.z * sc.z + sh.z; b.w = b.w * sc.w + sh.w;
    float dot = a.x * b.x + a.y * b.y + a.z * b.z + a.w * b.w;
#pragma unroll
    for (int off = 16; off > 0; off >>= 1)
        dot += __shfl_xor_sync(0xFFFFFFFF, dot, off);
    if (lane == 0) out[q] = dot;
}

// ---------------- host ----------------
extern "C" void kernel_launch(void* const* d_in, const int* in_sizes, int n_in,
                              void* d_out, int out_size) {
    const float* x  = (const float*)d_in[0];
    const float* Wl[3] = {(const float*)d_in[1], (const float*)d_in[5], (const float*)d_in[9]};
    const float* bl[3] = {(const float*)d_in[2], (const float*)d_in[6], (const float*)d_in[10]};
    const float* gl[3] = {(const float*)d_in[3], (const float*)d_in[7], (const float*)d_in[11]};
    const float* bel[3]= {(const float*)d_in[4], (const float*)d_in[8], (const float*)d_in[12]};
    const int* ei  = (const int*)d_in[13];
    const int* eli = (const int*)d_in[14];
    float* out = (float*)d_out;

    int N = in_sizes[0] / HD;
    int E = in_sizes[13] / 2;
    int Q = in_sizes[14] / 2;

    float *pL, *pG;
    cudaGetSymbolAddress((void**)&pL, g_L);
    cudaGetSymbolAddress((void**)&pG, g_G);

    cudaFuncSetAttribute(k_gemm, cudaFuncAttributeMaxDynamicSharedMemorySize, GEMM_SMEM);

    int nblk = (N + SCAN_CHUNK - 1) / SCAN_CHUNK;
    k_zero_cnt<<<(N + 255) / 256, 256>>>(N);
    k_hist<<<(E + 255) / 256, 256>>>(ei, E);
    k_dinv<<<(N + 255) / 256, 256>>>(N);
    k_blocksum<<<nblk, 256>>>(N);
    k_scan_bsum<<<1, 128>>>(E, N);
    k_emit<<<nblk, 256>>>(N);
    k_fill<<<(E + 255) / 256, 256>>>(ei, E);

    int gemm_blocks = (N + 127) / 128;
    int agg_blocks  = (N + 7) / 8;

    const float* in = x;
    for (int l = 0; l < 3; l++) {
        k_gemm<<<gemm_blocks, 256, GEMM_SMEM>>>(in, Wl[l], pL, N, l > 0 ? 1 : 0);
        k_zero_stats<<<1, 128>>>();
        k_aggregate<<<agg_blocks, 256>>>(pL, bl[l], pG, N);
        k_bn_final<<<1, 128>>>(gl[l], bel[l], N);
        in = pG;
    }

    k_query<<<(Q + 7) / 8, 256>>>(pG, eli, out, Q);
}

// round 8
// speedup vs baseline: 1.0088x; 1.0088x over previous
#include <cuda_runtime.h>
#include <cstdint>

#define HD 128
#define NMAX 100000
#define EMAX 800000
#define SCAN_CHUNK 1024
#define NBLK ((NMAX + SCAN_CHUNK - 1) / SCAN_CHUNK)

// ---------------- scratch ----------------
__device__ __align__(256) float g_L[(size_t)NMAX * HD];
__device__ __align__(256) float g_G[(size_t)NMAX * HD];
__device__ __align__(256) float g_dinv[NMAX];
__device__ __align__(256) float g_selfw[NMAX];
__device__ __align__(256) int   g_cnt[NMAX];
__device__ __align__(256) int   g_rowptr[NMAX + 1];
__device__ __align__(256) int   g_cursor[NMAX];
__device__ __align__(256) int   g_csrc[EMAX];
__device__ __align__(256) float g_cw[EMAX];
__device__ __align__(256) int   g_bsum[NBLK];
__device__ __align__(256) int   g_boff[NBLK];
__device__ __align__(256) float g_sum[HD];
__device__ __align__(256) float g_sq[HD];
__device__ __align__(256) float g_scale[HD];
__device__ __align__(256) float g_shift[HD];

// ---------------- CSR build ----------------
__global__ void k_zero_cnt(int N) {
    int i = blockIdx.x * blockDim.x + threadIdx.x;
    if (i < N) g_cnt[i] = 0;
}
__global__ void k_hist(const int* __restrict__ ei, int E) {
    int e = blockIdx.x * blockDim.x + threadIdx.x;
    if (e < E) atomicAdd(&g_cnt[ei[E + e]], 1);
}
__global__ void k_dinv(int N) {
    int i = blockIdx.x * blockDim.x + threadIdx.x;
    if (i < N) {
        float dv = rsqrtf((float)g_cnt[i] + 1.0f);
        g_dinv[i]  = dv;
        g_selfw[i] = dv * dv;
    }
}
__global__ void __launch_bounds__(256) k_blocksum(int N) {
    __shared__ int wsum[8];
    int tid  = threadIdx.x;
    int base = blockIdx.x * SCAN_CHUNK + tid * 4;
    int s = 0;
#pragma unroll
    for (int j = 0; j < 4; j++) {
        int i = base + j;
        if (i < N) s += g_cnt[i];
    }
#pragma unroll
    for (int off = 16; off > 0; off >>= 1)
        s += __shfl_down_sync(0xFFFFFFFF, s, off);
    if ((tid & 31) == 0) wsum[tid >> 5] = s;
    __syncthreads();
    if (tid == 0) {
        int t = 0;
#pragma unroll
        for (int w = 0; w < 8; w++) t += wsum[w];
        g_bsum[blockIdx.x] = t;
    }
}
__global__ void __launch_bounds__(128) k_scan_bsum(int E, int N) {
    __shared__ int sv[NBLK];
    int tid = threadIdx.x;
    if (tid < NBLK) sv[tid] = g_bsum[tid];
    __syncthreads();
    if (tid == 0) {
        int run = 0;
        for (int i = 0; i < NBLK; i++) {
            g_boff[i] = run;
            run += sv[i];
        }
        g_rowptr[N] = E;
    }
}
__global__ void __launch_bounds__(256) k_emit(int N) {
    __shared__ int wexc[8];
    int tid  = threadIdx.x;
    int lane = tid & 31;
    int wid  = tid >> 5;
    int base = blockIdx.x * SCAN_CHUNK + tid * 4;
    int c[4];
#pragma unroll
    for (int j = 0; j < 4; j++) {
        int i = base + j;
        c[j] = (i < N) ? g_cnt[i] : 0;
    }
    int tsum = c[0] + c[1] + c[2] + c[3];
    int inc = tsum;
#pragma unroll
    for (int off = 1; off < 32; off <<= 1) {
        int v = __shfl_up_sync(0xFFFFFFFF, inc, off);
        if (lane >= off) inc += v;
    }
    if (lane == 31) wexc[wid] = inc;
    __syncthreads();
    if (tid == 0) {
        int run = 0;
#pragma unroll
        for (int w = 0; w < 8; w++) {
            int t = wexc[w];
            wexc[w] = run;
            run += t;
        }
    }
    __syncthreads();
    int run = g_boff[blockIdx.x] + wexc[wid] + (inc - tsum);
#pragma unroll
    for (int j = 0; j < 4; j++) {
        int i = base + j;
        if (i < N) {
            g_rowptr[i] = run;
            g_cursor[i] = run;
            run += c[j];
        }
    }
}
__global__ void k_fill(const int* __restrict__ ei, int E) {
    int e = blockIdx.x * blockDim.x + threadIdx.x;
    if (e < E) {
        int s = ei[e], d = ei[E + e];
        int pos = atomicAdd(&g_cursor[d], 1);
        g_csrc[pos] = s;
        g_cw[pos]   = g_dinv[s] * g_dinv[d];
    }
}

// ---------------- packed f32x2 helpers ----------------
__device__ __forceinline__ unsigned long long pack2(float lo, float hi) {
    unsigned long long r;
    asm("mov.b64 %0, {%1, %2};" : "=l"(r) : "f"(lo), "f"(hi));
    return r;
}
__device__ __forceinline__ void unpack2(unsigned long long p, float& lo, float& hi) {
    asm("mov.b64 {%0, %1}, %2;" : "=f"(lo), "=f"(hi) : "l"(p));
}
__device__ __forceinline__ void fma2(unsigned long long& d, unsigned long long a,
                                     unsigned long long b) {
    asm("fma.rn.f32x2 %0, %1, %2, %0;" : "+l"(d) : "l"(a), "l"(b));
}

// ---------------- GEMM: L = act(A) @ W  (packed f32x2 FFMA) ----------------
// bn=0: act = identity; bn=1: act = relu(scale*A + shift)
__global__ void __launch_bounds__(256) k_gemm(const float* __restrict__ A,
                                              const float* __restrict__ W,
                                              float* __restrict__ L, int N, int bn) {
    extern __shared__ float sm[];
    float* As = sm;              // [k][row]  128*128
    float* Ws = sm + 128 * 128;  // [k][col]  128*128

    int tid   = threadIdx.x;
    int rbase = blockIdx.x * 128;

    for (int i = tid; i < 4096; i += 256)
        ((float4*)Ws)[i] = ((const float4*)W)[i];

    for (int i = tid; i < 4096; i += 256) {
        int row = i & 127;
        int kq  = i >> 7;
        int gr  = rbase + row;
        float4 v = make_float4(0.f, 0.f, 0.f, 0.f);
        if (gr < N) v = ((const float4*)(A + (size_t)gr * HD))[kq];
        if (bn) {
            float4 sc = ((const float4*)g_scale)[kq];
            float4 sh = ((const float4*)g_shift)[kq];
            v.x = fmaxf(v.x * sc.x + sh.x, 0.f);
            v.y = fmaxf(v.y * sc.y + sh.y, 0.f);
            v.z = fmaxf(v.z * sc.z + sh.z, 0.f);
            v.w = fmaxf(v.w * sc.w + sh.w, 0.f);
        }
        int k = kq * 4;
        As[(k + 0) * 128 + row] = v.x;
        As[(k + 1) * 128 + row] = v.y;
        As[(k + 2) * 128 + row] = v.z;
        As[(k + 3) * 128 + row] = v.w;
    }
    __syncthreads();

    int tr = tid >> 4, tc = tid & 15;
    int r0 = tr * 8, c0 = tc * 8;
    unsigned long long acc[8][4];
#pragma unroll
    for (int i = 0; i < 8; i++)
#pragma unroll
        for (int j = 0; j < 4; j++) acc[i][j] = 0ull;

#pragma unroll 4
    for (int k = 0; k < 128; k++) {
        float a[8], b[8];
        *(float4*)(a)     = *(float4*)&As[k * 128 + r0];
        *(float4*)(a + 4) = *(float4*)&As[k * 128 + r0 + 4];
        *(float4*)(b)     = *(float4*)&Ws[k * 128 + c0];
        *(float4*)(b + 4) = *(float4*)&Ws[k * 128 + c0 + 4];
        unsigned long long b2[4];
#pragma unroll
        for (int j = 0; j < 4; j++) b2[j] = pack2(b[2 * j], b[2 * j + 1]);
#pragma unroll
        for (int i = 0; i < 8; i++) {
            unsigned long long ad = pack2(a[i], a[i]);
#pragma unroll
            for (int j = 0; j < 4; j++) fma2(acc[i][j], ad, b2[j]);
        }
    }

#pragma unroll
    for (int i = 0; i < 8; i++) {
        int row = rbase + r0 + i;
        if (row < N) {
            float o[8];
#pragma unroll
            for (int j = 0; j < 4; j++) unpack2(acc[i][j], o[2 * j], o[2 * j + 1]);
            float4* cp = (float4*)(L + (size_t)row * HD + c0);
            cp[0] = make_float4(o[0], o[1], o[2], o[3]);
            cp[1] = make_float4(o[4], o[5], o[6], o[7]);
        }
    }
}

// ---------------- aggregate + fused BN stats ----------------
__global__ void __launch_bounds__(256) k_aggregate(const float* __restrict__ L,
                                                   const float* __restrict__ bias,
                                                   float* __restrict__ G, int N) {
    __shared__ float ssum[HD];
    __shared__ float ssq[HD];
    int tid  = threadIdx.x;
    int wid  = tid >> 5;
    int lane = tid & 31;
    int row  = blockIdx.x * 8 + wid;

    if (tid < HD) ssum[tid] = 0.f;
    else          ssq[tid - HD] = 0.f;
    __syncthreads();

    if (row < N) {
        float4 b  = ((const float4*)bias)[lane];
        float  sw = g_selfw[row];
        float4 sv = ((const float4*)(L + (size_t)row * HD))[lane];
        float4 acc;
        acc.x = sv.x * sw + b.x;
        acc.y = sv.y * sw + b.y;
        acc.z = sv.z * sw + b.z;
        acc.w = sv.w * sw + b.w;

        int p0 = g_rowptr[row], p1 = g_rowptr[row + 1];
        for (int p = p0; p < p1; p++) {
            int   s = g_csrc[p];
            float w = g_cw[p];
            float4 v = ((const float4*)(L + (size_t)s * HD))[lane];
            acc.x += v.x * w;
            acc.y += v.y * w;
            acc.z += v.z * w;
            acc.w += v.w * w;
        }
        ((float4*)(G + (size_t)row * HD))[lane] = acc;

        int c = lane * 4;
        atomicAdd(&ssum[c + 0], acc.x);
        atomicAdd(&ssum[c + 1], acc.y);
        atomicAdd(&ssum[c + 2], acc.z);
        atomicAdd(&ssum[c + 3], acc.w);
        atomicAdd(&ssq[c + 0], acc.x * acc.x);
        atomicAdd(&ssq[c + 1], acc.y * acc.y);
        atomicAdd(&ssq[c + 2], acc.z * acc.z);
        atomicAdd(&ssq[c + 3], acc.w * acc.w);
    }
    __syncthreads();
    if (tid < HD) atomicAdd(&g_sum[tid], ssum[tid]);
    else          atomicAdd(&g_sq[tid - HD], ssq[tid - HD]);
}

// ---------------- BN ----------------
__global__ void k_zero_stats() {
    int c = threadIdx.x;
    g_sum[c] = 0.f;
    g_sq[c]  = 0.f;
}
__global__ void k_bn_final(const float* __restrict__ gamma, const float* __restrict__ beta, int N) {
    int c = threadIdx.x;
    float invn = 1.0f / (float)N;
    float mu   = g_sum[c] * invn;
    float var  = g_sq[c] * invn - mu * mu;
    float sc   = gamma[c] * rsqrtf(var + 1e-5f);
    g_scale[c] = sc;
    g_shift[c] = beta[c] - mu * sc;
}

// ---------------- query ----------------
__global__ void k_query(const float* __restrict__ G, const int* __restrict__ eli,
                        float* __restrict__ out, int Q) {
    int gtid = blockIdx.x * blockDim.x + threadIdx.x;
    int q    = gtid >> 5;
    int lane = gtid & 31;
    if (q >= Q) return;
    int u = eli[q];
    int v = eli[Q + q];
    float4 sc = ((const float4*)g_scale)[lane];
    float4 sh = ((const float4*)g_shift)[lane];
    float4 a = ((const float4*)(G + (size_t)u * HD))[lane];
    float4 b = ((const float4*)(G + (size_t)v * HD))[lane];
    a.x = a.x * sc.x + sh.x; a.y = a.y * sc.y + sh.y;
    a.z = a.z * sc.z + sh.z; a.w = a.w * sc.w + sh.w;
    b.x = b.x * sc.x + sh.x; b.y = b.y * sc.y + sh.y;
    b.z = b.z * sc.z + sh.z; b.w = b.w * sc.w + sh.w;
    float dot = a.x * b.x + a.y * b.y + a.z * b.z + a.w * b.w;
#pragma unroll
    for (int off = 16; off > 0; off >>= 1)
        dot += __shfl_xor_sync(0xFFFFFFFF, dot, off);
    if (lane == 0) out[q] = dot;
}

// ---------------- host ----------------
extern "C" void kernel_launch(void* const* d_in, const int* in_sizes, int n_in,
                              void* d_out, int out_size) {
    const float* x  = (const float*)d_in[0];
    const float* Wl[3] = {(const float*)d_in[1], (const float*)d_in[5], (const float*)d_in[9]};
    const float* bl[3] = {(const float*)d_in[2], (const float*)d_in[6], (const float*)d_in[10]};
    const float* gl[3] = {(const float*)d_in[3], (const float*)d_in[7], (const float*)d_in[11]};
    const float* bel[3]= {(const float*)d_in[4], (const float*)d_in[8], (const float*)d_in[12]};
    const int* ei  = (const int*)d_in[13];
    const int* eli = (const int*)d_in[14];
    float* out = (float*)d_out;

    int N = in_sizes[0] / HD;
    int E = in_sizes[13] / 2;
    int Q = in_sizes[14] / 2;

    float *pL, *pG;
    cudaGetSymbolAddress((void**)&pL, g_L);
    cudaGetSymbolAddress((void**)&pG, g_G);

    const int GEMM_SMEM = 128 * 128 * 2 * sizeof(float);
    cudaFuncSetAttribute(k_gemm, cudaFuncAttributeMaxDynamicSharedMemorySize, GEMM_SMEM);

    int nblk = (N + SCAN_CHUNK - 1) / SCAN_CHUNK;
    k_zero_cnt<<<(N + 255) / 256, 256>>>(N);
    k_hist<<<(E + 255) / 256, 256>>>(ei, E);
    k_dinv<<<(N + 255) / 256, 256>>>(N);
    k_blocksum<<<nblk, 256>>>(N);
    k_scan_bsum<<<1, 128>>>(E, N);
    k_emit<<<nblk, 256>>>(N);
    k_fill<<<(E + 255) / 256, 256>>>(ei, E);

    int gemm_blocks = (N + 127) / 128;
    int agg_blocks  = (N + 7) / 8;

    const float* in = x;
    for (int l = 0; l < 3; l++) {
        k_gemm<<<gemm_blocks, 256, GEMM_SMEM>>>(in, Wl[l], pL, N, l > 0 ? 1 : 0);
        k_zero_stats<<<1, 128>>>();
        k_aggregate<<<agg_blocks, 256>>>(pL, bl[l], pG, N);
        k_bn_final<<<1, 128>>>(gl[l], bel[l], N);
        in = pG;
    }

    k_query<<<(Q + 7) / 8, 256>>>(pG, eli, out, Q);
}